// round 13
// baseline (speedup 1.0000x reference)
#include <cuda_runtime.h>

// Beamform_1649267442279 — GB300 sm_103a — R13: R8 (best: 58.5us kernel,
// DRAM 82.7%) + weights staged into __constant__ memory via a captured 32B
// D2D memcpy node. Weights move to the uniform/const path (LDCU->UR):
// removes the 2 broadcast LDGs per thread (~5% of L1 wavefronts), the
// weight-load dependency at warp start, and frees 8 regular registers.
//
// Semantics: per channel s, blocks of 20 complex samples (40 floats).
// Block b, row r (0..3), col c (0..4):
//   re[r,c] = in_s[40b + 10r + 2c],  im[r,c] = in_s[40b + 10r + 2c + 1]
//   out[(s*Bc+b)*10 + c]     = sum_r br[r]*re - bi[r]*im
//   out[(s*Bc+b)*10 + 5 + c] = sum_r bi[r]*re + br[r]*im
// with br[r]=bf[2r], bi[r]=bf[2r+1].
//
// Mapping (R8): thread (g, ch), g = b*5 + j, handles col j of blocks b and
// b + Bc/2. 8 independent front-batched LDG.64, two compact 1KB warp
// windows. Streaming stores (__stcs) keep L2 ways for load-side line reuse.

__constant__ float c_bf[8];

__global__ void __launch_bounds__(256)
beamform_kernel(const float* __restrict__ in0,
                const float* __restrict__ in1,
                const float* __restrict__ in2,
                const float* __restrict__ in3,
                float* __restrict__ out,
                int half_blocks,       // Bc / 2
                int blocks_per_ch)     // Bc
{
    const int g = blockIdx.x * blockDim.x + threadIdx.x;
    if (g >= half_blocks * 5) return;

    const int ch = blockIdx.y;
    const float* __restrict__ in =
        (ch == 0) ? in0 : (ch == 1) ? in1 : (ch == 2) ? in2 : in3;

    const int b = g / 5;            // block in first half
    const int j = g - b * 5;        // column 0..4

    // ---- front-batched loads: 8 independent LDG.64, two compact windows ----
    const float2* __restrict__ pA =
        (const float2*)(in + (size_t)b * 40 + 2 * j);
    const float2* __restrict__ pB = pA + (size_t)half_blocks * 20;  // +Bc/2

    const float2 a0 = __ldg(pA + 0);
    const float2 a1 = __ldg(pA + 5);
    const float2 a2 = __ldg(pA + 10);
    const float2 a3 = __ldg(pA + 15);
    const float2 c0 = __ldg(pB + 0);
    const float2 c1 = __ldg(pB + 5);
    const float2 c2 = __ldg(pB + 10);
    const float2 c3 = __ldg(pB + 15);

    // weights from constant bank (uniform path, no L1tex traffic)
    const float br0 = c_bf[0], bi0 = c_bf[1];
    const float br1 = c_bf[2], bi1 = c_bf[3];
    const float br2 = c_bf[4], bi2 = c_bf[5];
    const float br3 = c_bf[6], bi3 = c_bf[7];

    float reA = br0 * a0.x - bi0 * a0.y;
    float imA = bi0 * a0.x + br0 * a0.y;
    reA += br1 * a1.x - bi1 * a1.y;
    imA += bi1 * a1.x + br1 * a1.y;
    reA += br2 * a2.x - bi2 * a2.y;
    imA += bi2 * a2.x + br2 * a2.y;
    reA += br3 * a3.x - bi3 * a3.y;
    imA += bi3 * a3.x + br3 * a3.y;

    float reB = br0 * c0.x - bi0 * c0.y;
    float imB = bi0 * c0.x + br0 * c0.y;
    reB += br1 * c1.x - bi1 * c1.y;
    imB += bi1 * c1.x + br1 * c1.y;
    reB += br2 * c2.x - bi2 * c2.y;
    imB += bi2 * c2.x + br2 * c2.y;
    reB += br3 * c3.x - bi3 * c3.y;
    imB += bi3 * c3.x + br3 * c3.y;

    const size_t obA = ((size_t)ch * blocks_per_ch + (size_t)b) * 10;
    const size_t obB = obA + (size_t)half_blocks * 10;

    // streaming stores: output is never re-read, don't pollute L2
    __stcs(out + obA + j,     reA);
    __stcs(out + obA + 5 + j, imA);
    __stcs(out + obB + j,     reB);
    __stcs(out + obB + 5 + j, imB);
}

extern "C" void kernel_launch(void* const* d_in, const int* in_sizes, int n_in,
                              void* d_out, int out_size)
{
    const float* in0 = (const float*)d_in[0];
    const float* in1 = (const float*)d_in[1];
    const float* in2 = (const float*)d_in[2];
    const float* in3 = (const float*)d_in[3];
    const float* bf  = (const float*)d_in[4];
    float* out = (float*)d_out;

    const int N  = in_sizes[0];          // 20,000,000 floats / channel
    const int Bc = N / 40;               // 500,000 beam blocks per channel
    const int Hb = Bc / 2;               // 250,000 blocks in each half

    // Stage weights into constant memory. Device-to-device async copy:
    // graph-capturable (memcpy node), no allocation, 32 bytes.
    cudaMemcpyToSymbolAsync(c_bf, bf, 8 * sizeof(float), 0,
                            cudaMemcpyDeviceToDevice);

    const int threads = 256;
    const int n_thr = Hb * 5;            // 1.25M threads per channel
    dim3 grid((n_thr + threads - 1) / threads, 4);

    beamform_kernel<<<grid, threads>>>(in0, in1, in2, in3, out, Hb, Bc);
}

// round 14
// speedup vs baseline: 1.0615x; 1.0615x over previous
#include <cuda_runtime.h>

// Beamform_1649267442279 — GB300 sm_103a — R14: R8 (empirical optimum:
// 58.5us kernel, DRAM 82.7%, single graph node) with 320 threads/CTA so the
// (block, column) split is computed from threadIdx.x (320 % 5 == 0: the
// global-index 32-bit division disappears; first LDG issues earlier).
// Structure otherwise identical to R8:
//  - thread (g, ch) handles col j of blocks b and b + Bc/2
//  - 8 independent front-batched LDG.64, two compact 1KB warp windows
//  - __stcs streaming stores (output never re-read; keep L2 for the
//    4x-per-line load reuse)
//
// Semantics: per channel s, blocks of 20 complex samples (40 floats).
// Block b, row r (0..3), col c (0..4):
//   re[r,c] = in_s[40b + 10r + 2c],  im[r,c] = in_s[40b + 10r + 2c + 1]
//   out[(s*Bc+b)*10 + c]     = sum_r br[r]*re - bi[r]*im
//   out[(s*Bc+b)*10 + 5 + c] = sum_r bi[r]*re + br[r]*im
// with br[r]=bf[2r], bi[r]=bf[2r+1].

#define THREADS 320

__global__ void __launch_bounds__(THREADS)
beamform_kernel(const float* __restrict__ in0,
                const float* __restrict__ in1,
                const float* __restrict__ in2,
                const float* __restrict__ in3,
                const float* __restrict__ bf,
                float* __restrict__ out,
                int half_blocks,       // Bc / 2
                int blocks_per_ch)     // Bc
{
    const int t = threadIdx.x;
    // 320 % 5 == 0: per-CTA block base is blockIdx.x * 64, j from t only.
    const int b_loc = t / 5;                       // 0..63
    const int j     = t - b_loc * 5;               // 0..4
    const int b     = blockIdx.x * (THREADS / 5) + b_loc;
    if (b >= half_blocks) return;

    const int ch = blockIdx.y;
    const float* __restrict__ in =
        (ch == 0) ? in0 : (ch == 1) ? in1 : (ch == 2) ? in2 : in3;

    // ---- front-batched loads: 8 independent LDG.64, two compact windows ----
    const float2* __restrict__ pA =
        (const float2*)(in + (size_t)b * 40 + 2 * j);
    const float2* __restrict__ pB = pA + (size_t)half_blocks * 20;  // +Bc/2

    const float2 a0 = __ldg(pA + 0);
    const float2 a1 = __ldg(pA + 5);
    const float2 a2 = __ldg(pA + 10);
    const float2 a3 = __ldg(pA + 15);
    const float2 c0 = __ldg(pB + 0);
    const float2 c1 = __ldg(pB + 5);
    const float2 c2 = __ldg(pB + 10);
    const float2 c3 = __ldg(pB + 15);

    // weights: uniform-address broadcast, L1-resident
    const float4 w0 = __ldg((const float4*)bf);      // br0, bi0, br1, bi1
    const float4 w1 = __ldg((const float4*)bf + 1);  // br2, bi2, br3, bi3

    float reA = w0.x * a0.x - w0.y * a0.y;
    float imA = w0.y * a0.x + w0.x * a0.y;
    reA += w0.z * a1.x - w0.w * a1.y;
    imA += w0.w * a1.x + w0.z * a1.y;
    reA += w1.x * a2.x - w1.y * a2.y;
    imA += w1.y * a2.x + w1.x * a2.y;
    reA += w1.z * a3.x - w1.w * a3.y;
    imA += w1.w * a3.x + w1.z * a3.y;

    float reB = w0.x * c0.x - w0.y * c0.y;
    float imB = w0.y * c0.x + w0.x * c0.y;
    reB += w0.z * c1.x - w0.w * c1.y;
    imB += w0.w * c1.x + w0.z * c1.y;
    reB += w1.x * c2.x - w1.y * c2.y;
    imB += w1.y * c2.x + w1.x * c2.y;
    reB += w1.z * c3.x - w1.w * c3.y;
    imB += w1.w * c3.x + w1.z * c3.y;

    const size_t obA = ((size_t)ch * blocks_per_ch + (size_t)b) * 10;
    const size_t obB = obA + (size_t)half_blocks * 10;

    // streaming stores: output is never re-read, don't pollute L2
    __stcs(out + obA + j,     reA);
    __stcs(out + obA + 5 + j, imA);
    __stcs(out + obB + j,     reB);
    __stcs(out + obB + 5 + j, imB);
}

extern "C" void kernel_launch(void* const* d_in, const int* in_sizes, int n_in,
                              void* d_out, int out_size)
{
    const float* in0 = (const float*)d_in[0];
    const float* in1 = (const float*)d_in[1];
    const float* in2 = (const float*)d_in[2];
    const float* in3 = (const float*)d_in[3];
    const float* bf  = (const float*)d_in[4];
    float* out = (float*)d_out;

    const int N  = in_sizes[0];          // 20,000,000 floats / channel
    const int Bc = N / 40;               // 500,000 beam blocks per channel
    const int Hb = Bc / 2;               // 250,000 blocks in each half

    const int blocks_per_cta = THREADS / 5;                 // 64
    dim3 grid((Hb + blocks_per_cta - 1) / blocks_per_cta,   // 3907
              4);

    beamform_kernel<<<grid, THREADS>>>(in0, in1, in2, in3, bf, out, Hb, Bc);
}